// round 15
// baseline (speedup 1.0000x reference)
#include <cuda_runtime.h>
#include <cuda_fp16.h>
#include <cstdint>
#include <cstddef>

// ---------------- problem constants ----------------
#define LI_B 32
#define LI_S 256
#define LI_H 768
#define LI_BS (LI_B * LI_S)   // 8192

#define NKC 12                 // 768 / 64
// CTA: 128 s-rows x band W=8 window, 256 threads (8 warps of 16 rows)
// B-only smem ring: 4 stages x 144 rows x 128 B
#define STG_BYTES 18432

// smem layout (dynamic)
#define OFF_DK   0             // 32 f32
#define OFF_KMP  128           // 144 f32 (padded kmask indicator)
#define OFF_QM   768           // 128 f32
#define OFF_SH   1280          // 768 half: Ksum hi  [1280, 2816)
#define OFF_SL   2816          // 768 half: Ksum lo  [2816, 4352)
#define OFF_RED  4352          // 8 f32
#define OFF_STG  4608
#define SMEM_BYTES (OFF_STG + 4 * STG_BYTES)   // 78336

// normalized fp16 copies of Q and K + small per-batch tables
__device__ __align__(128) __half g_qh[LI_BS * LI_H];
__device__ __align__(128) __half g_kh[LI_BS * LI_H];
__device__ float g_S[LI_B][LI_H];     // masked key sums (f32)
__device__ float g_qmsum[LI_B];
__device__ float g_nv[LI_B];

// ---------------- helpers ----------------
__device__ __forceinline__ uint32_t smem_u32(const void* p) {
    uint32_t a;
    asm("{ .reg .u64 t; cvta.to.shared.u64 t, %1; cvt.u32.u64 %0, t; }"
        : "=r"(a) : "l"(p));
    return a;
}

__device__ __forceinline__ void ldsm_x4(uint32_t& r0, uint32_t& r1,
                                        uint32_t& r2, uint32_t& r3, uint32_t addr) {
    asm volatile("ldmatrix.sync.aligned.m8n8.x4.shared.b16 {%0,%1,%2,%3}, [%4];"
                 : "=r"(r0), "=r"(r1), "=r"(r2), "=r"(r3) : "r"(addr));
}

__device__ __forceinline__ void mma16816(float& c0, float& c1, float& c2, float& c3,
                                         uint32_t a0, uint32_t a1, uint32_t a2, uint32_t a3,
                                         uint32_t b0, uint32_t b1) {
    asm volatile(
        "mma.sync.aligned.m16n8k16.row.col.f32.f16.f16.f32 "
        "{%0,%1,%2,%3}, {%4,%5,%6,%7}, {%8,%9}, {%0,%1,%2,%3};"
        : "+f"(c0), "+f"(c1), "+f"(c2), "+f"(c3)
        : "r"(a0), "r"(a1), "r"(a2), "r"(a3), "r"(b0), "r"(b1));
}

__device__ __forceinline__ void cpa16(uint32_t dst, const void* src) {
    asm volatile("cp.async.cg.shared.global [%0], [%1], 16;"
                 :: "r"(dst), "l"(__cvta_generic_to_global(src)));
}

// ---------------- kernel 1: normalize rows to fp16 (warp per row) -----------
__global__ __launch_bounds__(256) void li_norm(const float* __restrict__ q,
                                               const float* __restrict__ k) {
    int wid = threadIdx.x >> 5, lane = threadIdx.x & 31;
    int row = blockIdx.x * 8 + wid;       // grid 2048 -> 16384 rows
    bool isq = row < LI_BS;
    int r = isq ? row : row - LI_BS;
    const float4* src = (const float4*)((isq ? q : k) + (size_t)r * LI_H);
    uint2* dst = (uint2*)((isq ? g_qh : g_kh) + (size_t)r * LI_H);

    float4 v[6];
    float ss = 0.f;
    #pragma unroll
    for (int it = 0; it < 6; it++) {
        v[it] = src[lane + 32 * it];
        ss += v[it].x * v[it].x + v[it].y * v[it].y
            + v[it].z * v[it].z + v[it].w * v[it].w;
    }
    #pragma unroll
    for (int o = 16; o; o >>= 1) ss += __shfl_xor_sync(0xFFFFFFFFu, ss, o);
    float inv = 1.f / fmaxf(sqrtf(ss), 1e-12f);

    #pragma unroll
    for (int it = 0; it < 6; it++) {
        __half2 h0 = __floats2half2_rn(v[it].x * inv, v[it].y * inv);
        __half2 h1 = __floats2half2_rn(v[it].z * inv, v[it].w * inv);
        uint2 o2;
        o2.x = *(uint32_t*)&h0;
        o2.y = *(uint32_t*)&h1;
        dst[lane + 32 * it] = o2;
    }
}

// ---------------- kernel 2: qmask sums + kmask counts + zero out ------------
__global__ __launch_bounds__(256) void li_prep(const float* __restrict__ qmask,
                                               const float* __restrict__ kmask,
                                               float* __restrict__ out) {
    int b = blockIdx.x, t = threadIdx.x;
    float v;
    if (b < 32) v = qmask[b * 256 + t];
    else        v = (kmask[(b - 32) * 256 + t] > 0.f) ? 1.f : 0.f;
    #pragma unroll
    for (int o = 16; o; o >>= 1) v += __shfl_xor_sync(0xFFFFFFFFu, v, o);
    __shared__ float red[8];
    if ((t & 31) == 0) red[t >> 5] = v;
    __syncthreads();
    if (t == 0) {
        float s = 0.f;
        #pragma unroll
        for (int w = 0; w < 8; w++) s += red[w];
        if (b < 32) g_qmsum[b] = fmaxf(s, 1.f);
        else        g_nv[b - 32] = s;
    }
    if (b < 32 && t < 32) out[b * 32 + t] = 0.f;
}

// ---------------- kernel 3: masked key sums (grid 32 x 4) -------------------
__global__ __launch_bounds__(192) void li_ksum(const float* __restrict__ kmask) {
    int j = blockIdx.x, col = blockIdx.y * 192 + threadIdx.x;
    __shared__ float kmI[256];
    for (int t = threadIdx.x; t < 256; t += 192)
        kmI[t] = (kmask[j * 256 + t] > 0.f) ? 1.f : 0.f;
    __syncthreads();
    const __half* kb = g_kh + (size_t)j * 256 * LI_H;
    float a = 0.f;
    for (int tt = 0; tt < 256; tt++)
        if (kmI[tt] != 0.f) a += __half2float(kb[(size_t)tt * LI_H + col]);
    g_S[j][col] = a;
}

// ---------------- kernel 4: band GEMM + rank-1 base + decay-softmax ----------
__global__ __launch_bounds__(256, 2) void li_band(
    const float* __restrict__ qmask, const float* __restrict__ kmask,
    const float* __restrict__ p_alpha, const float* __restrict__ p_lscale,
    float* __restrict__ out) {
    extern __shared__ char smem[];
    const uint32_t sb = smem_u32(smem);
    const int tid = threadIdx.x, wid = tid >> 5, lane = tid & 31;
    const int i = blockIdx.x >> 1, mhalf = blockIdx.x & 1;
    const int j = blockIdx.y;
    const int jbase = j * 256;
    const int qrow0 = i * 256 + mhalf * 128;

    float* dkS = (float*)(smem + OFF_DK);
    float* kmP = (float*)(smem + OFF_KMP);
    float* qmS = (float*)(smem + OFF_QM);
    __half2* Sh = (__half2*)(smem + OFF_SH);
    __half2* Sl = (__half2*)(smem + OFF_SL);
    float* redS = (float*)(smem + OFF_RED);

    const int tb0 = mhalf * 128 - 8;

    // tables
    {
        float araw = p_alpha[0];
        float alpha = fmaxf(araw, 0.f) + log1pf(__expf(-fabsf(araw)));
        float scale = __expf(p_lscale[0]);
        if (tid < 32) dkS[tid] = scale * __expf(-alpha * (float)tid);
        if (tid < 144) {
            int tpos = tb0 + tid;
            kmP[tid] = (tpos >= 0 && tpos < 256 && kmask[jbase + tpos] > 0.f)
                           ? 1.f : 0.f;
        }
        if (tid < 128) qmS[tid] = qmask[qrow0 + tid];
        #pragma unroll
        for (int idx = tid; idx < 384; idx += 256) {
            float s0 = g_S[j][2 * idx], s1 = g_S[j][2 * idx + 1];
            __half h0 = __float2half_rn(s0), h1 = __float2half_rn(s1);
            Sh[idx] = __halves2half2(h0, h1);
            Sl[idx] = __floats2half2_rn(s0 - __half2float(h0), s1 - __half2float(h1));
        }
    }
    const uint32_t stg0 = sb + OFF_STG;
    // zero B pad rows (8 rows at one end) in all 4 stages
    {
        int pad0 = (mhalf == 0) ? 0 : 136;
        int st = tid >> 6, rem = tid & 63;
        int pr = pad0 + (rem >> 3), c = rem & 7;
        uint32_t a = stg0 + st * STG_BYTES + pr * 128 + c * 16;
        asm volatile("st.shared.v4.b32 [%0], {%1,%1,%1,%1};"
                     :: "r"(a), "r"(0) : "memory");
    }

    // -------- B load pointers (chunk-invariant except +128B/chunk)
    const int r0 = tid >> 3, c8t = tid & 7;
    const char* gB = (const char*)(g_kh + (size_t)(jbase + tb0 + r0) * LI_H
                                   + c8t * 8);          // may be OOB; predicated
    const uint32_t swc = ((uint32_t)(c8t ^ (r0 & 7))) << 4;
    const uint32_t dB0 = (uint32_t)(r0 * 128) + swc;
    uint32_t vm = 0;
    #pragma unroll
    for (int l = 0; l < 5; l++) {
        int krow = tb0 + 32 * l + r0;
        bool v = (krow >= 0) && (krow < 256) && (l < 4 || tid < 128);
        vm |= (v ? 1u : 0u) << l;
    }

    // -------- A direct-LDG pointers (mma fragment layout)
    const char* gA0 = (const char*)(g_qh
        + (size_t)(qrow0 + 16 * wid + (lane >> 2)) * LI_H) + 4 * (lane & 3);
    const char* gA8 = gA0 + (size_t)8 * LI_H * 2;

    // -------- B ldsm address components
    const int l15 = lane & 15, hi = lane >> 4, l7 = lane & 7;
    const uint32_t cB0 = (uint32_t)((16 * wid + l15) * 128);
    const uint32_t cB1 = cB0 + 2048;
    uint32_t off[4];
    #pragma unroll
    for (int ks = 0; ks < 4; ks++) off[ks] = (uint32_t)(((2 * ks + hi) ^ l7) << 4);

    // prologue: B chunks 0..2 into buffers 0..2
    #pragma unroll
    for (int s = 0; s < 3; s++) {
        uint32_t stg = stg0 + s * STG_BYTES;
        #pragma unroll
        for (int l = 0; l < 5; l++)
            if (vm & (1u << l)) cpa16(stg + dB0 + 4096 * l, gB + 49152 * l);
        gB += 128;
        asm volatile("cp.async.commit_group;" ::: "memory");
    }

    float acc[4][4], accb[4];
    #pragma unroll
    for (int nt = 0; nt < 4; nt++)
        #pragma unroll
        for (int v = 0; v < 4; v++) acc[nt][v] = 0.f;
    #pragma unroll
    for (int v = 0; v < 4; v++) accb[v] = 0.f;

    // A double-buffer: load chunk 0
    uint32_t Aa[2][4][4];
    #pragma unroll
    for (int ks = 0; ks < 4; ks++) {
        Aa[0][ks][0] = *(const uint32_t*)(gA0 + ks * 32);
        Aa[0][ks][2] = *(const uint32_t*)(gA0 + ks * 32 + 16);
        Aa[0][ks][1] = *(const uint32_t*)(gA8 + ks * 32);
        Aa[0][ks][3] = *(const uint32_t*)(gA8 + ks * 32 + 16);
    }

    // mainloop: 3 outer x 4 buffers (single barrier per chunk)
    for (int ko = 0; ko < 3; ko++) {
        #pragma unroll
        for (int u = 0; u < 4; u++) {
            const int kc = ko * 4 + u;
            const uint32_t stg = stg0 + u * STG_BYTES;
            asm volatile("cp.async.wait_group 2;" ::: "memory");
            __syncthreads();

            // prefetch B chunk kc+3 into buffer (u+3)&3  (never the one being read)
            if (kc + 3 < NKC) {
                uint32_t stgN = stg0 + ((u + 3) & 3) * STG_BYTES;
                #pragma unroll
                for (int l = 0; l < 5; l++)
                    if (vm & (1u << l)) cpa16(stgN + dB0 + 4096 * l, gB + 49152 * l);
                gB += 128;
            }
            asm volatile("cp.async.commit_group;" ::: "memory");

            // hoisted B fragments for all 4 ks
            uint32_t Bf[4][8];
            #pragma unroll
            for (int ks = 0; ks < 4; ks++) {
                ldsm_x4(Bf[ks][0], Bf[ks][1], Bf[ks][2], Bf[ks][3],
                        stg + cB0 + off[ks]);
                ldsm_x4(Bf[ks][4], Bf[ks][5], Bf[ks][6], Bf[ks][7],
                        stg + cB1 + off[ks]);
            }

            // rank-1 pseudo-B fragments
            uint32_t pb0[4], pb1[4];
            #pragma unroll
            for (int ks = 0; ks < 4; ks++) {
                pb0[ks] = 0; pb1[ks] = 0;
                if (lane < 8) {
                    int kk2 = kc * 32 + 8 * ks;
                    int sub = lane & 3;
                    __half2 v0 = (lane < 4 ? Sh : Sl)[kk2 + sub];
                    __half2 v1 = (lane < 4 ? Sh : Sl)[kk2 + 4 + sub];
                    pb0[ks] = *(uint32_t*)&v0;
                    pb1[ks] = *(uint32_t*)&v1;
                }
            }

            // prefetch A for chunk kc+1 (registers)
            const int cur = kc & 1, nxt = cur ^ 1;
            if (kc + 1 < NKC) {
                const char* pA0 = gA0 + (kc + 1) * 128;
                const char* pA8 = gA8 + (kc + 1) * 128;
                #pragma unroll
                for (int ks = 0; ks < 4; ks++) {
                    Aa[nxt][ks][0] = *(const uint32_t*)(pA0 + ks * 32);
                    Aa[nxt][ks][2] = *(const uint32_t*)(pA0 + ks * 32 + 16);
                    Aa[nxt][ks][1] = *(const uint32_t*)(pA8 + ks * 32);
                    Aa[nxt][ks][3] = *(const uint32_t*)(pA8 + ks * 32 + 16);
                }
            }

            #pragma unroll
            for (int ks = 0; ks < 4; ks++) {
                uint32_t a0 = Aa[cur][ks][0], a1 = Aa[cur][ks][1];
                uint32_t a2 = Aa[cur][ks][2], a3 = Aa[cur][ks][3];
                mma16816(accb[0], accb[1], accb[2], accb[3],
                         a0, a1, a2, a3, pb0[ks], pb1[ks]);
                mma16816(acc[0][0], acc[0][1], acc[0][2], acc[0][3],
                         a0, a1, a2, a3, Bf[ks][0], Bf[ks][2]);
                mma16816(acc[1][0], acc[1][1], acc[1][2], acc[1][3],
                         a0, a1, a2, a3, Bf[ks][1], Bf[ks][3]);
                mma16816(acc[2][0], acc[2][1], acc[2][2], acc[2][3],
                         a0, a1, a2, a3, Bf[ks][4], Bf[ks][6]);
                mma16816(acc[3][0], acc[3][1], acc[3][2], acc[3][3],
                         a0, a1, a2, a3, Bf[ks][5], Bf[ks][7]);
            }
        }
    }
    asm volatile("cp.async.wait_group 0;" ::: "memory");

    // ---------------- epilogue ----------------
    const int lrow = lane >> 2;                 // 0..7
    float eA = 0.f, seA = 0.f, eB = 0.f, seB = 0.f;
    #pragma unroll
    for (int nt = 0; nt < 4; nt++) {
        int off0 = nt * 8 + (lane & 3) * 2;     // 0..31 within band window
        #pragma unroll
        for (int v = 0; v < 2; v++) {
            int offc = off0 + v;
            float km = kmP[16 * wid + offc];
            if (km > 0.f) {
                float sA_ = acc[nt][v], sB_ = acc[nt][2 + v];
                int dA = abs(lrow + 8 - offc);
                int dB = abs(lrow + 16 - offc);
                float cA_ = __expf(sA_ * dkS[dA]) - 1.f;
                float cB_ = __expf(sB_ * dkS[dB]) - 1.f;
                eA += cA_; seA += cA_ * sA_;
                eB += cB_; seB += cB_ * sB_;
            }
        }
    }
    #pragma unroll
    for (int o = 1; o <= 2; o <<= 1) {
        eA  += __shfl_xor_sync(0xFFFFFFFFu, eA, o);
        seA += __shfl_xor_sync(0xFFFFFFFFu, seA, o);
        eB  += __shfl_xor_sync(0xFFFFFFFFu, eB, o);
        seB += __shfl_xor_sync(0xFFFFFFFFu, seB, o);
    }

    float val = 0.f;
    if ((lane & 3) == 0) {
        float NvJ = g_nv[j];
        float baseA = accb[0] + accb[1];   // cols 0(hi) + 1(lo)
        float baseB = accb[2] + accb[3];
        float suA = NvJ + eA, suB = NvJ + eB;
        float scA = (suA > 0.f) ? (baseA + seA) / suA : 0.f;
        float scB = (suB > 0.f) ? (baseB + seB) / suB : 0.f;
        val = scA * qmS[16 * wid + lrow] + scB * qmS[16 * wid + lrow + 8];
    }
    #pragma unroll
    for (int o = 16; o; o >>= 1) val += __shfl_xor_sync(0xFFFFFFFFu, val, o);
    if (lane == 0) redS[wid] = val;
    __syncthreads();
    if (tid == 0) {
        float tot = 0.f;
        #pragma unroll
        for (int w = 0; w < 8; w++) tot += redS[w];
        atomicAdd(&out[i * 32 + j], tot / g_qmsum[i]);
    }
}

// ---------------- launch ----------------
extern "C" void kernel_launch(void* const* d_in, const int* in_sizes, int n_in,
                              void* d_out, int out_size) {
    const float* q  = (const float*)d_in[0];
    const float* k  = (const float*)d_in[1];
    const float* qm = (const float*)d_in[2];
    const float* km = (const float*)d_in[3];
    const float* al = (const float*)d_in[4];
    const float* ls = (const float*)d_in[5];
    float* out = (float*)d_out;

    cudaFuncSetAttribute(li_band, cudaFuncAttributeMaxDynamicSharedMemorySize,
                         SMEM_BYTES);

    li_norm<<<2048, 256>>>(q, k);
    li_prep<<<64, 256>>>(qm, km, out);
    li_ksum<<<dim3(32, 4), 192>>>(km);
    li_band<<<dim3(64, 32), 256, SMEM_BYTES>>>(qm, km, al, ls, out);
}